// round 10
// baseline (speedup 1.0000x reference)
#include <cuda_runtime.h>
#include <math.h>

#define N_NODES 10000
#define N_EDGES 160000
#define H       128
#define F3H     384
#define E_RBF   20
#define L_LAYERS 3
#define PI_F    3.14159265358979f
#define CUTOFF_F 5.0f

#define NPB 8     // nodes per block (scalar_out / readout), chunked accumulators
#define NPU 8     // nodes per block (update), smem-stashed Uv/Vv
#define NGB 4     // nodes per block (aggregate) — proven R5

// ---------- persistent scratch ----------
__device__ float g_ns  [N_NODES * H];
__device__ float g_ns2 [N_NODES * H];
__device__ float g_vecA[N_NODES * 3 * H];
__device__ float g_vecB[N_NODES * 3 * H];
__device__ float g_so  [N_NODES * F3H];

// CSR / sorted edge data (built once per launch)
__device__ int    g_rowptr[N_NODES + 1];
__device__ int    g_cursor[N_NODES];
__device__ int    g_src_s [N_EDGES];
__device__ float4 g_geo_s [N_EDGES];             // {fcut, u0, u1, u2}
__device__ float  g_rbf_s [N_EDGES * E_RBF];

__device__ __forceinline__ float silu_f(float x) {
    return x / (1.0f + expf(-x));
}

// ---------- CSR build ----------
__global__ void k_zero_cnt() {
    int i = blockIdx.x * blockDim.x + threadIdx.x;
    if (i < N_NODES) g_cursor[i] = 0;
}

__global__ void k_hist(const int* __restrict__ edge) {
    int e = blockIdx.x * blockDim.x + threadIdx.x;
    if (e < N_EDGES) atomicAdd(&g_cursor[edge[2 * e]], 1);
}

__global__ void __launch_bounds__(1024) k_scan() {
    __shared__ int s_part[1024];
    int tid = threadIdx.x;
    const int CH = 10;
    int base = tid * CH;
    int local[CH];
    int sum = 0;
#pragma unroll
    for (int i = 0; i < CH; i++) {
        int idx = base + i;
        int v = (idx < N_NODES) ? g_cursor[idx] : 0;
        local[i] = sum;
        sum += v;
    }
    s_part[tid] = sum;
    __syncthreads();
    for (int off = 1; off < 1024; off <<= 1) {
        int add = (tid >= off) ? s_part[tid - off] : 0;
        __syncthreads();
        s_part[tid] += add;
        __syncthreads();
    }
    int excl = (tid > 0) ? s_part[tid - 1] : 0;
#pragma unroll
    for (int i = 0; i < CH; i++) {
        int idx = base + i;
        if (idx < N_NODES) {
            int rp = excl + local[i];
            g_rowptr[idx] = rp;
            g_cursor[idx] = rp;
        }
    }
    if (tid == 0) g_rowptr[N_NODES] = N_EDGES;
}

__global__ void k_scatter(const int* __restrict__ edge,
                          const float* __restrict__ ediff,
                          const float* __restrict__ edist) {
    int e = blockIdx.x * blockDim.x + threadIdx.x;
    if (e >= N_EDGES) return;
    int dst = edge[2 * e], src = edge[2 * e + 1];
    int pos = atomicAdd(&g_cursor[dst], 1);
    g_src_s[pos] = src;
    float dist = edist[e];
    float fcut = (dist < CUTOFF_F) ? 0.5f * (cosf(PI_F * dist / CUTOFF_F) + 1.0f) : 0.0f;
    float inv = 1.0f / dist;
    float4 geo;
    geo.x = fcut;
    geo.y = ediff[3 * e + 0] * inv;
    geo.z = ediff[3 * e + 1] * inv;
    geo.w = ediff[3 * e + 2] * inv;
    g_geo_s[pos] = geo;
    float4* rb4 = reinterpret_cast<float4*>(g_rbf_s + (size_t)pos * E_RBF);
#pragma unroll
    for (int q = 0; q < E_RBF / 4; q++) {
        float4 v;
        v.x = sinf(dist * (float)(4 * q + 1) * (PI_F / CUTOFF_F)) * inv;
        v.y = sinf(dist * (float)(4 * q + 2) * (PI_F / CUTOFF_F)) * inv;
        v.z = sinf(dist * (float)(4 * q + 3) * (PI_F / CUTOFF_F)) * inv;
        v.w = sinf(dist * (float)(4 * q + 4) * (PI_F / CUTOFF_F)) * inv;
        rb4[q] = v;
    }
}

// ---------- init ----------
__global__ void __launch_bounds__(H) k_init(const int* __restrict__ z,
                                            const float* __restrict__ embed) {
    int i = blockIdx.x, j = threadIdx.x;
    g_ns[i * H + j] = embed[z[i] * H + j];
#pragma unroll
    for (int d = 0; d < 3; d++) g_vecA[i * 3 * H + d * H + j] = 0.0f;
}

// ---------- scalar_out: NPB=8, chunked W2 stage ----------
__global__ void __launch_bounds__(H) k_scalar_out(const float* __restrict__ W1,
                                                  const float* __restrict__ b1,
                                                  const float* __restrict__ W2,
                                                  const float* __restrict__ b2) {
    int i0 = blockIdx.x * NPB, j = threadIdx.x;
    __shared__ float s_x[NPB][H];
    __shared__ float s_h[NPB][H];
#pragma unroll
    for (int n = 0; n < NPB; n++) s_x[n][j] = g_ns[(i0 + n) * H + j];
    __syncthreads();

    {
        float acc[NPB];
        float bb = b1[j];
#pragma unroll
        for (int n = 0; n < NPB; n++) acc[n] = bb;
        for (int k = 0; k < H; k++) {
            float w = W1[k * H + j];
#pragma unroll
            for (int n = 0; n < NPB; n++) acc[n] += s_x[n][k] * w;
        }
#pragma unroll
        for (int n = 0; n < NPB; n++) s_h[n][j] = silu_f(acc[n]);
    }
    __syncthreads();

#pragma unroll 1
    for (int c = 0; c < 3; c++) {
        float a[NPB];
        float bb = b2[c * H + j];
#pragma unroll
        for (int n = 0; n < NPB; n++) a[n] = bb;
        for (int k = 0; k < H; k++) {
            float w = W2[k * F3H + c * H + j];
#pragma unroll
            for (int n = 0; n < NPB; n++) a[n] += s_h[n][k] * w;
        }
#pragma unroll
        for (int n = 0; n < NPB; n++)
            g_so[(size_t)(i0 + n) * F3H + c * H + j] = a[n];
    }
}

// ---------- aggregate: filter weights in registers (proven R5) ----------
__global__ void __launch_bounds__(H) k_aggregate(const float* __restrict__ Fw,
                                                 const float* __restrict__ Fb) {
    int j = threadIdx.x;

    float rw0[E_RBF], rw1[E_RBF], rw2[E_RBF];
#pragma unroll
    for (int k = 0; k < E_RBF; k++) {
        rw0[k] = Fw[k * F3H + j];
        rw1[k] = Fw[k * F3H + H + j];
        rw2[k] = Fw[k * F3H + 2 * H + j];
    }
    float rb0 = Fb[j], rb1 = Fb[H + j], rb2 = Fb[2 * H + j];

    int n0 = blockIdx.x * NGB;
    for (int n = n0; n < n0 + NGB; n++) {
        int r0 = g_rowptr[n], r1 = g_rowptr[n + 1];
        float accs = 0.0f, av0 = 0.0f, av1 = 0.0f, av2 = 0.0f;
#pragma unroll 2
        for (int p = r0; p < r1; p++) {
            int src = g_src_s[p];
            float4 geo = g_geo_s[p];
            const float4* rbf4 = reinterpret_cast<const float4*>(g_rbf_s + (size_t)p * E_RBF);
            float4 rA = rbf4[0], rB = rbf4[1], rC = rbf4[2], rD = rbf4[3], rE = rbf4[4];
            float rbf[E_RBF] = {rA.x, rA.y, rA.z, rA.w, rB.x, rB.y, rB.z, rB.w,
                                rC.x, rC.y, rC.z, rC.w, rD.x, rD.y, rD.z, rD.w,
                                rE.x, rE.y, rE.z, rE.w};

            float fw0 = rb0, fw1 = rb1, fw2 = rb2;
#pragma unroll
            for (int k = 0; k < E_RBF; k++) {
                fw0 += rbf[k] * rw0[k];
                fw1 += rbf[k] * rw1[k];
                fw2 += rbf[k] * rw2[k];
            }

            const float* so = g_so + (size_t)src * F3H;
            float fcut = geo.x;
            float gsv = fw0 * (fcut * so[j]);
            float gev = fw1 * (fcut * so[H + j]);
            accs += fw2 * (fcut * so[2 * H + j]);

            const float* vin = g_vecA + (size_t)src * 3 * H;
            av0 += vin[j]         * gsv + gev * geo.y;
            av1 += vin[H + j]     * gsv + gev * geo.z;
            av2 += vin[2 * H + j] * gsv + gev * geo.w;
        }
        g_ns2[(size_t)n * H + j] = g_ns[(size_t)n * H + j] + accs;
        float* vo = g_vecB + (size_t)n * 3 * H;
        const float* va = g_vecA + (size_t)n * 3 * H;
        vo[j]         = va[j]         + av0;
        vo[H + j]     = va[H + j]     + av1;
        vo[2 * H + j] = va[2 * H + j] + av2;
    }
}

// ---------- update: NPU=8, Uv/Vv stashed to smem, chunked MLP ----------
__global__ void __launch_bounds__(H) k_update(const float* __restrict__ Uw,
                                              const float* __restrict__ Ub,
                                              const float* __restrict__ Vw,
                                              const float* __restrict__ Vb,
                                              const float* __restrict__ W1,
                                              const float* __restrict__ b1,
                                              const float* __restrict__ W2,
                                              const float* __restrict__ b2) {
    int i0 = blockIdx.x * NPU, j = threadIdx.x;
    __shared__ float s_v [NPU][3 * H];   // 12 KB
    __shared__ float s_uv[NPU][3 * H];   // 12 KB
    __shared__ float s_vv[NPU][3 * H];   // 12 KB
    __shared__ float s_in[NPU][2 * H];   // 8 KB
    __shared__ float s_h [NPU][H];       // 4 KB

#pragma unroll
    for (int n = 0; n < NPU; n++) {
#pragma unroll
        for (int d = 0; d < 3; d++)
            s_v[n][d * H + j] = g_vecB[(size_t)(i0 + n) * 3 * H + d * H + j];
        s_in[n][H + j] = g_ns2[(size_t)(i0 + n) * H + j];
    }
    __syncthreads();

    // Stage A: Uv/Vv matvecs (48 accumulators, stashed to smem after)
    {
        float Uv[NPU][3], Vv[NPU][3];
        float ub = Ub[j], vb = Vb[j];
#pragma unroll
        for (int n = 0; n < NPU; n++)
#pragma unroll
            for (int d = 0; d < 3; d++) { Uv[n][d] = ub; Vv[n][d] = vb; }

        for (int k = 0; k < H; k++) {
            float u = Uw[k * H + j];
            float v = Vw[k * H + j];
#pragma unroll
            for (int n = 0; n < NPU; n++)
#pragma unroll
                for (int d = 0; d < 3; d++) {
                    float x = s_v[n][d * H + k];
                    Uv[n][d] += x * u;
                    Vv[n][d] += x * v;
                }
        }
#pragma unroll
        for (int n = 0; n < NPU; n++) {
#pragma unroll
            for (int d = 0; d < 3; d++) {
                s_uv[n][d * H + j] = Uv[n][d];
                s_vv[n][d * H + j] = Vv[n][d];
            }
            s_in[n][j] = sqrtf(Vv[n][0] * Vv[n][0] + Vv[n][1] * Vv[n][1] + Vv[n][2] * Vv[n][2]);
        }
    }
    __syncthreads();

    // Stage B: hidden = silu(mlp_in @ W1 + b1)
    {
        float acc[NPU];
        float bb = b1[j];
#pragma unroll
        for (int n = 0; n < NPU; n++) acc[n] = bb;
        for (int k = 0; k < 2 * H; k++) {
            float w = W1[k * H + j];
#pragma unroll
            for (int n = 0; n < NPU; n++) acc[n] += s_in[n][k] * w;
        }
#pragma unroll
        for (int n = 0; n < NPU; n++) s_h[n][j] = silu_f(acc[n]);
    }
    __syncthreads();

    // Stage C: chunked W2 passes (a_vv, a_sv, a_ss), 8 accumulators each
    float a0[NPU], a1[NPU], a2[NPU];
#pragma unroll 1
    for (int c = 0; c < 3; c++) {
        float a[NPU];
        float bb = b2[c * H + j];
#pragma unroll
        for (int n = 0; n < NPU; n++) a[n] = bb;
        for (int k = 0; k < H; k++) {
            float w = W2[k * F3H + c * H + j];
#pragma unroll
            for (int n = 0; n < NPU; n++) a[n] += s_h[n][k] * w;
        }
#pragma unroll
        for (int n = 0; n < NPU; n++) {
            if (c == 0) a0[n] = a[n];
            else if (c == 1) a1[n] = a[n];
            else a2[n] = a[n];
        }
    }

    // Final writes
#pragma unroll
    for (int n = 0; n < NPU; n++) {
        float dot = 0.0f;
#pragma unroll
        for (int d = 0; d < 3; d++) {
            float uv = s_uv[n][d * H + j];
            g_vecA[(size_t)(i0 + n) * 3 * H + d * H + j] = s_v[n][d * H + j] + a0[n] * uv;
            dot += uv * s_vv[n][d * H + j];
        }
        g_ns[(size_t)(i0 + n) * H + j] = s_in[n][H + j] + a1[n] * dot + a2[n];
    }
}

// ---------- readout: NPB=8 ----------
__global__ void __launch_bounds__(H) k_readout(const float* __restrict__ W1,
                                               const float* __restrict__ b1,
                                               const float* __restrict__ W2,
                                               const float* __restrict__ b2,
                                               float* __restrict__ out) {
    int i0 = blockIdx.x * NPB, j = threadIdx.x;
    __shared__ float s_x[NPB][H];
    __shared__ float s_h[NPB][H];
#pragma unroll
    for (int n = 0; n < NPB; n++) s_x[n][j] = g_ns[(i0 + n) * H + j];
    __syncthreads();

    {
        float acc[NPB];
        float bb = b1[j];
#pragma unroll
        for (int n = 0; n < NPB; n++) acc[n] = bb;
        for (int k = 0; k < H; k++) {
            float w = W1[k * H + j];
#pragma unroll
            for (int n = 0; n < NPB; n++) acc[n] += s_x[n][k] * w;
        }
#pragma unroll
        for (int n = 0; n < NPB; n++) s_h[n][j] = silu_f(acc[n]);
    }
    __syncthreads();

    float a[NPB];
    float c = b2[j];
#pragma unroll
    for (int n = 0; n < NPB; n++) a[n] = c;
    for (int k = 0; k < H; k++) {
        float w = W2[k * H + j];
#pragma unroll
        for (int n = 0; n < NPB; n++) a[n] += s_h[n][k] * w;
    }
#pragma unroll
    for (int n = 0; n < NPB; n++) out[(i0 + n) * H + j] = a[n];
}

// ---------- host launcher ----------
extern "C" void kernel_launch(void* const* d_in, const int* in_sizes, int n_in,
                              void* d_out, int out_size) {
    const int*   z      = (const int*)  d_in[0];
    const int*   edge   = (const int*)  d_in[1];
    const float* ediff  = (const float*)d_in[2];
    const float* edist  = (const float*)d_in[3];
    const float* embed  = (const float*)d_in[4];
    const float* mfw    = (const float*)d_in[5];
    const float* mfb    = (const float*)d_in[6];
    const float* mw1    = (const float*)d_in[7];
    const float* mb1    = (const float*)d_in[8];
    const float* mw2    = (const float*)d_in[9];
    const float* mb2    = (const float*)d_in[10];
    const float* uUw    = (const float*)d_in[11];
    const float* uUb    = (const float*)d_in[12];
    const float* uVw    = (const float*)d_in[13];
    const float* uVb    = (const float*)d_in[14];
    const float* uw1    = (const float*)d_in[15];
    const float* ub1    = (const float*)d_in[16];
    const float* uw2    = (const float*)d_in[17];
    const float* ub2    = (const float*)d_in[18];
    const float* row1   = (const float*)d_in[19];
    const float* rob1   = (const float*)d_in[20];
    const float* row2   = (const float*)d_in[21];
    const float* rob2   = (const float*)d_in[22];
    float* out = (float*)d_out;

    k_zero_cnt<<<(N_NODES + 255) / 256, 256>>>();
    k_hist<<<(N_EDGES + 255) / 256, 256>>>(edge);
    k_scan<<<1, 1024>>>();
    k_scatter<<<(N_EDGES + 255) / 256, 256>>>(edge, ediff, edist);

    k_init<<<N_NODES, H>>>(z, embed);

    for (int l = 0; l < L_LAYERS; l++) {
        k_scalar_out<<<N_NODES / NPB, H>>>(mw1 + l * H * H, mb1 + l * H,
                                           mw2 + l * H * F3H, mb2 + l * F3H);
        k_aggregate<<<N_NODES / NGB, H>>>(mfw + l * E_RBF * F3H, mfb + l * F3H);
        k_update<<<N_NODES / NPU, H>>>(uUw + l * H * H, uUb + l * H,
                                       uVw + l * H * H, uVb + l * H,
                                       uw1 + l * 2 * H * H, ub1 + l * H,
                                       uw2 + l * H * F3H, ub2 + l * F3H);
    }
    k_readout<<<N_NODES / NPB, H>>>(row1, rob1, row2, rob2, out);
}